// round 1
// baseline (speedup 1.0000x reference)
#include <cuda_runtime.h>
#include <cstdint>

// ---------------------------------------------------------------------------
// Problem constants (fixed shapes: x [8,16,512,512] f32)
// ---------------------------------------------------------------------------
#define HH 512
#define WW 512
#define NU 257          // rfft width = W/2+1
#define SU 260          // padded u-stride (float2), keeps rows 16B-aligned
#define NCH 16
#define NBATCH 8
#define IMGS (NBATCH*NCH)   // 128

// Scratch spectra: [img][h][u] as float2, padded stride SU.
__device__ float2 g_X[(size_t)IMGS * HH * SU];
__device__ float2 g_Y[(size_t)IMGS * HH * SU];

__device__ __forceinline__ int rev9(int i) {
    return (int)(__brev((unsigned)i) >> 23);
}

// In-place radix-2 DIT 512-point FFT on shared array `a` (bit-reversed input
// order). NT threads of a group participate (group index tg in [0,NT)).
// Uses block-wide __syncthreads(): every group in the block must run this
// with identical trip counts (they do).
__device__ __forceinline__ void fft512_shared(float2* a, int tg, int NT, float sign) {
    #pragma unroll
    for (int s = 1; s <= 9; ++s) {
        const int half = 1 << (s - 1);
        const float base = sign * 6.283185307179586f / (float)(1 << s);
        for (int b = tg; b < 256; b += NT) {
            const int pos = b & (half - 1);
            const int i = ((b >> (s - 1)) << s) + pos;
            const int j = i + half;
            float sn, cs;
            __sincosf(base * (float)pos, &sn, &cs);
            const float2 t = a[j];
            const float2 u = a[i];
            const float tr = t.x * cs - t.y * sn;
            const float ti = t.x * sn + t.y * cs;
            a[i] = make_float2(u.x + tr, u.y + ti);
            a[j] = make_float2(u.x - tr, u.y - ti);
        }
        __syncthreads();
    }
}

// ---------------------------------------------------------------------------
// Kernel A: row rfft. Two real rows packed into one complex 512-pt FFT.
// grid = 128 imgs * 256 row-pairs = 32768 blocks, 128 threads.
// ---------------------------------------------------------------------------
__global__ __launch_bounds__(128) void kA_rfft_rows(const float* __restrict__ x) {
    __shared__ float2 sh[512];
    const int blk = blockIdx.x;
    const int img = blk >> 8;
    const int pr  = blk & 255;
    const int t = threadIdx.x;

    const float* r0 = x + ((size_t)img * HH + 2 * pr) * WW;
    const float* r1 = r0 + WW;

    #pragma unroll
    for (int k = t; k < 512; k += 128)
        sh[rev9(k)] = make_float2(r0[k], r1[k]);
    __syncthreads();

    fft512_shared(sh, t, 128, -1.0f);

    float2* X0 = g_X + ((size_t)img * HH + 2 * pr) * SU;
    float2* X1 = X0 + SU;
    for (int k = t; k < NU; k += 128) {
        const int m = (512 - k) & 511;
        const float2 zk = sh[k];
        const float2 zm = sh[m];
        // R1 = (Z[k] + conj(Z[-k]))/2 ; R2 = (Z[k] - conj(Z[-k]))/(2i)
        X0[k] = make_float2(0.5f * (zk.x + zm.x), 0.5f * (zk.y - zm.y));
        X1[k] = make_float2(0.5f * (zk.y + zm.y), -0.5f * (zk.x - zm.x));
    }
}

// ---------------------------------------------------------------------------
// Kernel B/D: column FFT along h. 4 columns per block, 512 threads
// (128 threads per column group). useY selects buffer; sign ±1; scale
// applied at store (kD folds the irfftn backward norm 1/512^2).
// grid = (ceil(257/4)=65, 128 imgs)
// ---------------------------------------------------------------------------
__global__ __launch_bounds__(512) void kBD_fft_cols(int useY, float sign, float scale) {
    __shared__ float2 sh[4][512];
    const int t = threadIdx.x;
    const int col = t & 3;
    const int tg = t >> 2;              // 0..127
    const int img = blockIdx.y;
    const int u = blockIdx.x * 4 + col;
    const bool ok = (u < NU);

    float2* data = useY ? g_Y : g_X;
    float2* base = data + (size_t)img * HH * SU + u;

    #pragma unroll
    for (int r = 0; r < 4; ++r) {
        const int h = tg + r * 128;
        float2 v = ok ? base[(size_t)h * SU] : make_float2(0.f, 0.f);
        sh[col][rev9(h)] = v;
    }
    __syncthreads();

    fft512_shared(sh[col], tg, 128, sign);

    if (ok) {
        #pragma unroll
        for (int r = 0; r < 4; ++r) {
            const int h = tg + r * 128;
            const float2 v = sh[col][h];
            base[(size_t)h * SU] = make_float2(v.x * scale, v.y * scale);
        }
    }
}

// ---------------------------------------------------------------------------
// Kernel C: 3x3 complex conv with 16->16 channel mixing on the spectrum.
// Reference math: Y[n,o,h,u] = sum_{i,a,b} w[i,o,a,b] * X[n,i,h+1-a,u+1-b]
// (zero padding), complex weights (wr, wi), plus bias.
// Tile: TH=16 x TU=32 points; 256 threads; each thread: 4 points x 8 outch.
// Dynamic smem: X tile (16ch x 18 x 35 float2) + weights (2*2304 floats).
// ---------------------------------------------------------------------------
#define TH 16
#define TU 32
#define SXW 35   // padded tile row width (need 34)
#define SX_ELEMS (NCH * (TH + 2) * SXW)
#define W_ELEMS (NCH * NCH * 9)   // 2304

__global__ __launch_bounds__(256, 2) void kC_conv(
    const float* __restrict__ w_real, const float* __restrict__ w_imag,
    const float* __restrict__ b_real, const float* __restrict__ b_imag)
{
    extern __shared__ float smemC[];
    float2* sX  = (float2*)smemC;                 // [16][18][35]
    float*  swr = (float*)(sX + SX_ELEMS);        // [(i*9+tap)*16+o]
    float*  swi = swr + W_ELEMS;

    const int t = threadIdx.x;
    const int u0 = blockIdx.x * TU;
    const int h0 = blockIdx.y * TH;
    const int n  = blockIdx.z;

    // Load weights: swr[(i*9+tap)*16+o] = w_real[(i*16+o)*9+tap]
    for (int idx = t; idx < W_ELEMS; idx += 256) {
        const int i = idx / 144;
        const int q = idx - i * 144;
        const int tap = q >> 4;
        const int o = q & 15;
        const int src = (i * 16 + o) * 9 + tap;
        swr[idx] = w_real[src];
        swi[idx] = w_imag[src];
    }

    // Load X tile with halo: channels 0..15, rows h0-1..h0+16, cols u0-1..u0+32
    for (int e = t; e < NCH * (TH + 2) * (TU + 2); e += 256) {
        const int i = e / ((TH + 2) * (TU + 2));
        const int q = e - i * ((TH + 2) * (TU + 2));
        const int rr = q / (TU + 2);
        const int cc = q - rr * (TU + 2);
        const int gh = h0 - 1 + rr;
        const int gu = u0 - 1 + cc;
        float2 v = make_float2(0.f, 0.f);
        if (gh >= 0 && gh < HH && gu >= 0 && gu < NU)
            v = g_X[(((size_t)n * NCH + i) * HH + gh) * SU + gu];
        sX[(i * (TH + 2) + rr) * SXW + cc] = v;
    }
    __syncthreads();

    // Thread work assignment: 4 points (same column, rows 4 apart) x 8 outch
    const int oh = t >> 7;            // out-channel half (0/1)
    const int ps = t & 127;
    const int lh0 = ps >> 5;          // base local row (0..3), +4*r
    const int lu  = ps & 31;          // local col

    float accr[4][8], acci[4][8];
    #pragma unroll
    for (int r = 0; r < 4; ++r)
        #pragma unroll
        for (int o = 0; o < 8; ++o) { accr[r][o] = 0.f; acci[r][o] = 0.f; }

    for (int i = 0; i < NCH; ++i) {
        #pragma unroll
        for (int a = 0; a < 3; ++a) {
            #pragma unroll
            for (int b = 0; b < 3; ++b) {
                float2 xv[4];
                #pragma unroll
                for (int r = 0; r < 4; ++r)
                    xv[r] = sX[(i * (TH + 2) + (lh0 + 4 * r + 2 - a)) * SXW + (lu + 2 - b)];
                const int wbase = (i * 9 + a * 3 + b) * 16 + oh * 8;
                #pragma unroll
                for (int o = 0; o < 8; ++o) {
                    const float wr_ = swr[wbase + o];
                    const float wi_ = swi[wbase + o];
                    #pragma unroll
                    for (int r = 0; r < 4; ++r) {
                        accr[r][o] += xv[r].x * wr_ - xv[r].y * wi_;
                        acci[r][o] += xv[r].x * wi_ + xv[r].y * wr_;
                    }
                }
            }
        }
    }

    const int u = u0 + lu;
    if (u < NU) {
        #pragma unroll
        for (int o = 0; o < 8; ++o) {
            const int og = oh * 8 + o;
            const float br_ = b_real[og];
            const float bi_ = b_imag[og];
            #pragma unroll
            for (int r = 0; r < 4; ++r) {
                const int h = h0 + lh0 + 4 * r;
                g_Y[(((size_t)n * NCH + og) * HH + h) * SU + u] =
                    make_float2(accr[r][o] + br_, acci[r][o] + bi_);
            }
        }
    }
}

// ---------------------------------------------------------------------------
// Kernel E: row irfft (257 complex -> 512 real), two rows per block via the
// packed trick. Im at u in {0,256} is zeroed first (true irfft semantics
// drop them), which makes the Hermitian packing exact.
// ---------------------------------------------------------------------------
__global__ __launch_bounds__(128) void kE_irfft_rows(float* __restrict__ out) {
    __shared__ float2 sg1[NU], sg2[NU];
    __shared__ float2 sh[512];
    const int blk = blockIdx.x;
    const int img = blk >> 8;
    const int pr  = blk & 255;
    const int t = threadIdx.x;

    const float2* G0 = g_Y + ((size_t)img * HH + 2 * pr) * SU;
    const float2* G1 = G0 + SU;

    for (int k = t; k < NU; k += 128) {
        float2 a = G0[k];
        float2 b = G1[k];
        if (k == 0 || k == 256) { a.y = 0.f; b.y = 0.f; }
        sg1[k] = a; sg2[k] = b;
    }
    __syncthreads();

    #pragma unroll
    for (int k = t; k < 512; k += 128) {
        float2 z;
        if (k <= 256) {
            const float2 a = sg1[k], b = sg2[k];
            z = make_float2(a.x - b.y, a.y + b.x);       // a + i*b
        } else {
            const int m = 512 - k;
            const float2 a = sg1[m], b = sg2[m];
            z = make_float2(a.x + b.y, b.x - a.y);       // conj(a - i*b)
        }
        sh[rev9(k)] = z;
    }
    __syncthreads();

    fft512_shared(sh, t, 128, +1.0f);

    float* o0 = out + ((size_t)img * HH + 2 * pr) * WW;
    float* o1 = o0 + WW;
    #pragma unroll
    for (int k = t; k < 512; k += 128) {
        o0[k] = sh[k].x;
        o1[k] = sh[k].y;
    }
}

// ---------------------------------------------------------------------------
// Launch
// ---------------------------------------------------------------------------
extern "C" void kernel_launch(void* const* d_in, const int* in_sizes, int n_in,
                              void* d_out, int out_size) {
    const float* x      = (const float*)d_in[0];
    const float* w_real = (const float*)d_in[1];
    const float* w_imag = (const float*)d_in[2];
    const float* b_real = (const float*)d_in[3];
    const float* b_imag = (const float*)d_in[4];
    float* out = (float*)d_out;

    const int smemC_bytes = SX_ELEMS * (int)sizeof(float2) + 2 * W_ELEMS * (int)sizeof(float);
    cudaFuncSetAttribute(kC_conv, cudaFuncAttributeMaxDynamicSharedMemorySize, smemC_bytes);

    // 1) row rfft
    kA_rfft_rows<<<IMGS * (HH / 2), 128>>>(x);

    // 2) forward column FFT over h
    dim3 gB((NU + 3) / 4, IMGS);
    kBD_fft_cols<<<gB, 512>>>(0, -1.0f, 1.0f);

    // 3) 3x3 complex conv + bias in frequency domain
    dim3 gC((NU + TU - 1) / TU, HH / TH, NBATCH);
    kC_conv<<<gC, 256, smemC_bytes>>>(w_real, w_imag, b_real, b_imag);

    // 4) inverse column FFT over h, with total backward-norm scale 1/(512*512)
    kBD_fft_cols<<<gB, 512>>>(1, +1.0f, 1.0f / (512.0f * 512.0f));

    // 5) row irfft -> real output
    kE_irfft_rows<<<IMGS * (HH / 2), 128>>>(out);
}

// round 2
// speedup vs baseline: 2.0280x; 2.0280x over previous
#include <cuda_runtime.h>
#include <cstdint>

// ---------------------------------------------------------------------------
// Problem constants (fixed shapes: x [8,16,512,512] f32)
// ---------------------------------------------------------------------------
#define HH 512
#define WW 512
#define NU 257          // rfft width = W/2+1
#define SU 260          // padded u-stride (float2)
#define NCH 16
#define NBATCH 8
#define IMGS (NBATCH*NCH)   // 128
#define GSTR 578            // per-FFT-group smem stride (float2); 578 % 16 == 2

// Scratch spectra: [img][h][u] as float2, padded stride SU.
__device__ float2 g_X[(size_t)IMGS * HH * SU];
__device__ float2 g_Y[(size_t)IMGS * HH * SU];

__device__ __forceinline__ float2 cmul(float2 a, float2 b) {
    return make_float2(a.x*b.x - a.y*b.y, a.x*b.y + a.y*b.x);
}
__device__ __forceinline__ float2 cadd(float2 a, float2 b) { return make_float2(a.x+b.x, a.y+b.y); }
__device__ __forceinline__ float2 csub(float2 a, float2 b) { return make_float2(a.x-b.x, a.y-b.y); }

// ---------------------------------------------------------------------------
// Radix-8 butterfly in registers. S = -1 forward, +1 inverse.
// Computes y[k] = sum_j a[j] * exp(S*2*pi*i*j*k/8), output in natural order.
// ---------------------------------------------------------------------------
template<int S>
__device__ __forceinline__ void fft8(float2 a[8]) {
    const float r = 0.7071067811865476f;
    const float sf = (float)S;
    float2 d, u;
    // stage 1: (j, j+4), twiddle W8^j on the difference
    u=a[0]; d=csub(u,a[4]); a[0]=cadd(u,a[4]); a[4]=d;
    u=a[1]; d=csub(u,a[5]); a[1]=cadd(u,a[5]); a[5]=make_float2(r*(d.x - sf*d.y), r*(sf*d.x + d.y));
    u=a[2]; d=csub(u,a[6]); a[2]=cadd(u,a[6]); a[6]=make_float2(-sf*d.y, sf*d.x);
    u=a[3]; d=csub(u,a[7]); a[3]=cadd(u,a[7]); a[7]=make_float2(r*(-d.x - sf*d.y), r*(sf*d.x - d.y));
    // stage 2: (j, j+2) within each 4-group, twiddle W4^1 = (0, S)
    u=a[0]; d=csub(u,a[2]); a[0]=cadd(u,a[2]); a[2]=d;
    u=a[1]; d=csub(u,a[3]); a[1]=cadd(u,a[3]); a[3]=make_float2(-sf*d.y, sf*d.x);
    u=a[4]; d=csub(u,a[6]); a[4]=cadd(u,a[6]); a[6]=d;
    u=a[5]; d=csub(u,a[7]); a[5]=cadd(u,a[7]); a[7]=make_float2(-sf*d.y, sf*d.x);
    // stage 3: adjacent pairs, no twiddle
    u=a[0]; a[0]=cadd(u,a[1]); a[1]=csub(u,a[1]);
    u=a[2]; a[2]=cadd(u,a[3]); a[3]=csub(u,a[3]);
    u=a[4]; a[4]=cadd(u,a[5]); a[5]=csub(u,a[5]);
    u=a[6]; a[6]=cadd(u,a[7]); a[7]=csub(u,a[7]);
    // bit-reverse rename to natural order: swap 1<->4, 3<->6
    d=a[1]; a[1]=a[4]; a[4]=d;
    d=a[3]; a[3]=a[6]; a[6]=d;
}

// ---------------------------------------------------------------------------
// 512-pt FFT: 64 threads (t in [0,64)), 8 float2 regs per thread.
// Input:  a[m] = x[t + 64*m]
// Output: a[m] = X[t + 64*m]
// s: per-group shared buffer, >= 576 float2. 3 block-wide __syncthreads inside
// (every thread of the block must call this with identical control flow).
// ---------------------------------------------------------------------------
template<int S>
__device__ __forceinline__ void fft512_regs(float2 a[8], int t, float2* s) {
    const float TWO_PI = 6.283185307179586f;
    const int n2 = t & 7;
    const int n1 = t >> 3;

    fft8<S>(a);  // regs now indexed by k0
    // twiddle W_64^{n1*k0}
    const float c1 = (float)S * TWO_PI / 64.0f * (float)n1;
    #pragma unroll
    for (int k0 = 1; k0 < 8; ++k0) {
        float sn, cs; __sincosf(c1 * (float)k0, &sn, &cs);
        a[k0] = cmul(a[k0], make_float2(cs, sn));
    }
    // exchange 1: write [ (n2+8*n1) + 72*k0 ], read regs over n1
    #pragma unroll
    for (int k0 = 0; k0 < 8; ++k0) s[t + 72*k0] = a[k0];
    __syncthreads();
    const int k0r = t >> 3;   // new role: (n2, k0)
    #pragma unroll
    for (int j = 0; j < 8; ++j) a[j] = s[n2 + 8*j + 72*k0r];
    __syncthreads();          // buffer reuse barrier

    fft8<S>(a);  // regs now indexed by k1
    // twiddle W_512^{n2*(k0 + 8*k1)}
    const float c2 = (float)S * TWO_PI / 512.0f * (float)n2;
    #pragma unroll
    for (int k1 = 0; k1 < 8; ++k1) {
        float sn, cs; __sincosf(c2 * (float)(k0r + 8*k1), &sn, &cs);
        a[k1] = cmul(a[k1], make_float2(cs, sn));
    }
    // exchange 2: XOR-swizzled [ 72*k1 + 8*k0 + (n2^k0) ]
    #pragma unroll
    for (int k1 = 0; k1 < 8; ++k1) s[72*k1 + 8*k0r + (n2 ^ k0r)] = a[k1];
    __syncthreads();
    const int k0b = t & 7, k1r = t >> 3;  // new role: (k0, k1), tid = k0 + 8*k1
    #pragma unroll
    for (int j = 0; j < 8; ++j) a[j] = s[72*k1r + 8*k0b + (j ^ k0b)];

    fft8<S>(a);  // regs now indexed by k2 ; X[t + 64*k2] = a[k2]
}

// ---------------------------------------------------------------------------
// Kernel A: row rfft. 512 threads = 8 FFT groups = 16 rows per block.
// Two real rows packed into one complex 512-pt FFT, then Hermitian unpack.
// grid = 128 imgs * 32 = 4096 blocks.
// ---------------------------------------------------------------------------
__global__ __launch_bounds__(512) void kA_rfft_rows(const float* __restrict__ x) {
    __shared__ float2 s[8 * GSTR];
    const int t = threadIdx.x & 63;
    const int g = threadIdx.x >> 6;
    const int img = blockIdx.x >> 5;
    const int seg = blockIdx.x & 31;
    const int pr = seg * 8 + g;           // row-pair 0..255

    const float* r0 = x + ((size_t)img * HH + 2 * pr) * WW;
    const float* r1 = r0 + WW;

    float2 a[8];
    #pragma unroll
    for (int m = 0; m < 8; ++m)
        a[m] = make_float2(r0[t + 64*m], r1[t + 64*m]);

    float2* z = s + g * GSTR;
    fft512_regs<-1>(a, t, z);

    __syncthreads();                       // exchange reads done everywhere
    #pragma unroll
    for (int m = 0; m < 8; ++m) z[t + 64*m] = a[m];
    __syncthreads();

    float2* X0 = g_X + ((size_t)img * HH + 2 * pr) * SU;
    float2* X1 = X0 + SU;
    #pragma unroll
    for (int m = 0; m < 5; ++m) {
        const int u = t + 64*m;
        if (u < NU) {
            const float2 zk = z[u];
            const float2 zm = z[(512 - u) & 511];
            X0[u] = make_float2(0.5f*(zk.x + zm.x),  0.5f*(zk.y - zm.y));
            X1[u] = make_float2(0.5f*(zk.y + zm.y), -0.5f*(zk.x - zm.x));
        }
    }
}

// ---------------------------------------------------------------------------
// Kernel B/D: column FFT along h. 512 threads = 8 u-columns per block
// (u is the FAST thread index for coalescing). grid = (33, 128).
// ---------------------------------------------------------------------------
template<int S>
__global__ __launch_bounds__(512) void kBD_fft_cols(int useY, float scale) {
    __shared__ float2 s[8 * GSTR];
    const int g = threadIdx.x & 7;        // u offset within block
    const int t = threadIdx.x >> 3;       // position in FFT (0..63)
    const int img = blockIdx.y;
    const int u = blockIdx.x * 8 + g;
    const bool ok = (u < NU);

    float2* data = useY ? g_Y : g_X;
    float2* base = data + (size_t)img * HH * SU + u;

    float2 a[8];
    #pragma unroll
    for (int m = 0; m < 8; ++m)
        a[m] = ok ? base[(size_t)(t + 64*m) * SU] : make_float2(0.f, 0.f);

    fft512_regs<S>(a, t, s + g * GSTR);

    if (ok) {
        #pragma unroll
        for (int m = 0; m < 8; ++m)
            base[(size_t)(t + 64*m) * SU] = make_float2(a[m].x * scale, a[m].y * scale);
    }
}

// ---------------------------------------------------------------------------
// Kernel C: 3x3 complex conv with 16->16 channel mixing on the spectrum.
// Y[n,o,h,u] = sum_{i,a,b} w[i,o,a,b] * X[n,i,h+1-a,u+1-b] + bias (zero pad).
// ---------------------------------------------------------------------------
#define TH 16
#define TU 32
#define SXW 35
#define SX_ELEMS (NCH * (TH + 2) * SXW)
#define W_ELEMS (NCH * NCH * 9)

__global__ __launch_bounds__(256, 2) void kC_conv(
    const float* __restrict__ w_real, const float* __restrict__ w_imag,
    const float* __restrict__ b_real, const float* __restrict__ b_imag)
{
    extern __shared__ float smemC[];
    float2* sX  = (float2*)smemC;
    float*  swr = (float*)(sX + SX_ELEMS);
    float*  swi = swr + W_ELEMS;

    const int t = threadIdx.x;
    const int u0 = blockIdx.x * TU;
    const int h0 = blockIdx.y * TH;
    const int n  = blockIdx.z;

    for (int idx = t; idx < W_ELEMS; idx += 256) {
        const int i = idx / 144;
        const int q = idx - i * 144;
        const int tap = q >> 4;
        const int o = q & 15;
        const int src = (i * 16 + o) * 9 + tap;
        swr[idx] = w_real[src];
        swi[idx] = w_imag[src];
    }

    for (int e = t; e < NCH * (TH + 2) * (TU + 2); e += 256) {
        const int i = e / ((TH + 2) * (TU + 2));
        const int q = e - i * ((TH + 2) * (TU + 2));
        const int rr = q / (TU + 2);
        const int cc = q - rr * (TU + 2);
        const int gh = h0 - 1 + rr;
        const int gu = u0 - 1 + cc;
        float2 v = make_float2(0.f, 0.f);
        if (gh >= 0 && gh < HH && gu >= 0 && gu < NU)
            v = g_X[(((size_t)n * NCH + i) * HH + gh) * SU + gu];
        sX[(i * (TH + 2) + rr) * SXW + cc] = v;
    }
    __syncthreads();

    const int oh = t >> 7;
    const int ps = t & 127;
    const int lh0 = ps >> 5;
    const int lu  = ps & 31;

    float accr[4][8], acci[4][8];
    #pragma unroll
    for (int r = 0; r < 4; ++r)
        #pragma unroll
        for (int o = 0; o < 8; ++o) { accr[r][o] = 0.f; acci[r][o] = 0.f; }

    for (int i = 0; i < NCH; ++i) {
        #pragma unroll
        for (int a = 0; a < 3; ++a) {
            #pragma unroll
            for (int b = 0; b < 3; ++b) {
                float2 xv[4];
                #pragma unroll
                for (int r = 0; r < 4; ++r)
                    xv[r] = sX[(i * (TH + 2) + (lh0 + 4 * r + 2 - a)) * SXW + (lu + 2 - b)];
                const int wbase = (i * 9 + a * 3 + b) * 16 + oh * 8;
                #pragma unroll
                for (int o = 0; o < 8; ++o) {
                    const float wr_ = swr[wbase + o];
                    const float wi_ = swi[wbase + o];
                    #pragma unroll
                    for (int r = 0; r < 4; ++r) {
                        accr[r][o] += xv[r].x * wr_ - xv[r].y * wi_;
                        acci[r][o] += xv[r].x * wi_ + xv[r].y * wr_;
                    }
                }
            }
        }
    }

    const int u = u0 + lu;
    if (u < NU) {
        #pragma unroll
        for (int o = 0; o < 8; ++o) {
            const int og = oh * 8 + o;
            const float br_ = b_real[og];
            const float bi_ = b_imag[og];
            #pragma unroll
            for (int r = 0; r < 4; ++r) {
                const int h = h0 + lh0 + 4 * r;
                g_Y[(((size_t)n * NCH + og) * HH + h) * SU + u] =
                    make_float2(accr[r][o] + br_, acci[r][o] + bi_);
            }
        }
    }
}

// ---------------------------------------------------------------------------
// Kernel E: row irfft. 512 threads = 8 groups = 16 rows per block.
// Hermitian pack (Im at u in {0,256} zeroed -> exact), inverse 512-pt FFT.
// ---------------------------------------------------------------------------
__global__ __launch_bounds__(512) void kE_irfft_rows(float* __restrict__ out) {
    __shared__ float2 s[8 * GSTR];
    const int t = threadIdx.x & 63;
    const int g = threadIdx.x >> 6;
    const int img = blockIdx.x >> 5;
    const int seg = blockIdx.x & 31;
    const int pr = seg * 8 + g;

    const float2* G0 = g_Y + ((size_t)img * HH + 2 * pr) * SU;
    const float2* G1 = G0 + SU;

    float2* z = s + g * GSTR;
    #pragma unroll
    for (int m = 0; m < 5; ++m) {
        const int u = t + 64*m;
        if (u < NU) {
            float2 A = G0[u];
            float2 B = G1[u];
            if (u == 0 || u == 256) { A.y = 0.f; B.y = 0.f; }
            z[u] = make_float2(A.x - B.y, A.y + B.x);            // A + i*B
            if (u >= 1 && u <= 255)
                z[512 - u] = make_float2(A.x + B.y, B.x - A.y);  // conj ext
        }
    }
    __syncthreads();

    float2 a[8];
    #pragma unroll
    for (int m = 0; m < 8; ++m) a[m] = z[t + 64*m];
    __syncthreads();       // all reads done before fft writes into z

    fft512_regs<+1>(a, t, z);

    float* o0 = out + ((size_t)img * HH + 2 * pr) * WW;
    float* o1 = o0 + WW;
    #pragma unroll
    for (int m = 0; m < 8; ++m) {
        o0[t + 64*m] = a[m].x;
        o1[t + 64*m] = a[m].y;
    }
}

// ---------------------------------------------------------------------------
// Launch
// ---------------------------------------------------------------------------
extern "C" void kernel_launch(void* const* d_in, const int* in_sizes, int n_in,
                              void* d_out, int out_size) {
    const float* x      = (const float*)d_in[0];
    const float* w_real = (const float*)d_in[1];
    const float* w_imag = (const float*)d_in[2];
    const float* b_real = (const float*)d_in[3];
    const float* b_imag = (const float*)d_in[4];
    float* out = (float*)d_out;

    const int smemC_bytes = SX_ELEMS * (int)sizeof(float2) + 2 * W_ELEMS * (int)sizeof(float);
    cudaFuncSetAttribute(kC_conv, cudaFuncAttributeMaxDynamicSharedMemorySize, smemC_bytes);

    // 1) row rfft
    kA_rfft_rows<<<IMGS * 32, 512>>>(x);

    // 2) forward column FFT over h
    dim3 gB((NU + 7) / 8, IMGS);
    kBD_fft_cols<-1><<<gB, 512>>>(0, 1.0f);

    // 3) 3x3 complex conv + bias in frequency domain
    dim3 gC((NU + TU - 1) / TU, HH / TH, NBATCH);
    kC_conv<<<gC, 256, smemC_bytes>>>(w_real, w_imag, b_real, b_imag);

    // 4) inverse column FFT over h, folding the backward norm 1/(512*512)
    kBD_fft_cols<+1><<<gB, 512>>>(1, 1.0f / (512.0f * 512.0f));

    // 5) row irfft -> real output
    kE_irfft_rows<<<IMGS * 32, 512>>>(out);
}